// round 13
// baseline (speedup 1.0000x reference)
#include <cuda_runtime.h>

#define HH 768
#define WW 768
#define CC 64
#define NSEG 385
#define NTHREADS 64
#define PER_T (HH / NTHREADS)     // 12 mask elems per scan thread
#define GRID_A 4736               // 148 SM x 32 CTA slots
#define NWARPS_TOTAL (GRID_A * 2)

// ---- scratch (device globals; no allocations allowed) ----
__device__ float4 g_cellmean[(size_t)NSEG * NSEG * 16];   // ~38MB cap, ~9.4MB used
__device__ int    g_row_id_d[HH];
__device__ int    g_col_id_d[WW];
__device__ int    g_ncol_d;

// ---------------------------------------------------------------------------
// Kernel A: per-cell means (R8-exact sum loop), no broadcast.
//   prolog: every block redundantly scans both masks -> SMEM segment tables;
//           block 0 additionally publishes per-pixel row/col ids + ncol.
//   main:   warp-per-cell, lanes = 16 channel-quads x 2 x-parities,
//           warp access = 512B contiguous, ONE shfl_xor(16) reduce,
//           256B result store to compact cellmean (stays in L2 for kernel B).
//   __ldcs on input: single-use stream, evict-first, keep L2 for cellmean.
// ---------------------------------------------------------------------------
__global__ void __launch_bounds__(NTHREADS, 32)
sum_kernel(const float* __restrict__ in,
           const int* __restrict__ h_mask,
           const int* __restrict__ v_mask) {
    __shared__ int s_row_start[NSEG + 1];
    __shared__ int s_col_start[NSEG + 1];
    __shared__ int s_tmp[2];
    __shared__ int s_nrow, s_ncol;

    const int t = threadIdx.x;
    const int lane = t & 31, w = t >> 5;
    const bool pub = (blockIdx.x == 0);

    // ---- prolog: build segment starts for both masks ----
    #pragma unroll
    for (int axis = 0; axis < 2; ++axis) {
        const int* m = (axis == 0) ? h_mask : v_mask;
        int* start   = (axis == 0) ? s_row_start : s_col_start;
        int* gid     = (axis == 0) ? g_row_id_d : g_col_id_d;

        const int base = t * PER_T;
        int pm = (base == 0) ? 1 : m[base - 1];   // pm=1 at i=0 forces rise[0]=0
        int rises = 0, cnt = 0;
        #pragma unroll
        for (int k = 0; k < PER_T; ++k) {
            const int mv = m[base + k];
            const int r = (mv == 1 && pm == 0);
            rises |= (r << k);
            cnt += r;
            pm = mv;
        }
        int v = cnt;
        #pragma unroll
        for (int o = 1; o < 32; o <<= 1) {
            int n = __shfl_up_sync(0xFFFFFFFFu, v, o);
            if (lane >= o) v += n;
        }
        if (lane == 31) s_tmp[w] = v;
        __syncthreads();
        const int add   = (w == 1) ? s_tmp[0] : 0;
        const int total = s_tmp[0] + s_tmp[1];
        const int excl  = v + add - cnt;

        int sid = excl;
        #pragma unroll
        for (int k = 0; k < PER_T; ++k) {
            if ((rises >> k) & 1) { ++sid; start[sid] = base + k; }
            if (pub) gid[base + k] = sid;
        }
        const int nseg = total + 1;
        if (t == 0) {
            start[0] = 0; start[nseg] = HH;
            if (axis == 0) s_nrow = nseg;
            else { s_ncol = nseg; if (pub) g_ncol_d = nseg; }
        }
        __syncthreads();
    }

    const int nrow = s_nrow, ncol = s_ncol;
    const int total_cells = nrow * ncol;

    const int cg = lane & 15;     // channel quad
    const int xo = lane >> 4;     // x parity
    const int gw = blockIdx.x * 2 + w;

    // ---- main: warp-per-cell grid-stride (R8-exact, unroll 2) ----
    for (int cell = gw; cell < total_cells; cell += NWARPS_TOTAL) {
        const int rseg = cell / ncol;
        const int cseg = cell - rseg * ncol;
        const int cs = s_col_start[cseg], ce = s_col_start[cseg + 1];
        const int rs = s_row_start[rseg], re = s_row_start[rseg + 1];

        float4 a0 = make_float4(0.f, 0.f, 0.f, 0.f);
        float4 a1 = make_float4(0.f, 0.f, 0.f, 0.f);

        int y = rs;
        for (; y + 1 < re; y += 2) {
            const float4* r0 = reinterpret_cast<const float4*>(
                in + (size_t)y * WW * CC);
            const float4* r1 = r0 + WW * (CC / 4);
            #pragma unroll 2
            for (int x = cs + xo; x < ce; x += 2) {
                const float4 v0 = __ldcs(&r0[x * 16 + cg]);
                const float4 v1 = __ldcs(&r1[x * 16 + cg]);
                a0.x += v0.x; a0.y += v0.y; a0.z += v0.z; a0.w += v0.w;
                a1.x += v1.x; a1.y += v1.y; a1.z += v1.z; a1.w += v1.w;
            }
        }
        if (y < re) {
            const float4* r0 = reinterpret_cast<const float4*>(
                in + (size_t)y * WW * CC);
            #pragma unroll 2
            for (int x = cs + xo; x < ce; x += 2) {
                const float4 v0 = __ldcs(&r0[x * 16 + cg]);
                a0.x += v0.x; a0.y += v0.y; a0.z += v0.z; a0.w += v0.w;
            }
        }
        a0.x += a1.x; a0.y += a1.y; a0.z += a1.z; a0.w += a1.w;

        // single-stage reduce across the two x parities (lanes +-16)
        a0.x += __shfl_xor_sync(0xFFFFFFFFu, a0.x, 16);
        a0.y += __shfl_xor_sync(0xFFFFFFFFu, a0.y, 16);
        a0.z += __shfl_xor_sync(0xFFFFFFFFu, a0.z, 16);
        a0.w += __shfl_xor_sync(0xFFFFFFFFu, a0.w, 16);

        if (xo == 0) {
            const float inv = 1.0f / (float)((re - rs) * (ce - cs));
            g_cellmean[(size_t)cell * 16 + cg] =
                make_float4(a0.x * inv, a0.y * inv, a0.z * inv, a0.w * inv);
        }
    }
}

// ---------------------------------------------------------------------------
// Kernel B: broadcast. One float4 per thread, perfectly balanced streaming.
//   warp = 32 consecutive float4 = 2 whole pixels -> row_id broadcast,
//   cellmean gather hits 2 L2-resident 256B lines, stores fully coalesced.
//   __stcs: output is never re-read; don't pollute L2.
// ---------------------------------------------------------------------------
__global__ void __launch_bounds__(256)
bcast_kernel(float4* __restrict__ out) {
    const int idx = blockIdx.x * 256 + threadIdx.x;   // exactly H*W*16 threads
    const int q = idx & 15;
    const int p = idx >> 4;
    const int y = p / WW;
    const int x = p - y * WW;
    const int cell = __ldg(&g_row_id_d[y]) * g_ncol_d + __ldg(&g_col_id_d[x]);
    const float4 v = __ldg(&g_cellmean[(size_t)cell * 16 + q]);
    __stcs(&out[idx], v);
}

// ---------------------------------------------------------------------------
extern "C" void kernel_launch(void* const* d_in, const int* in_sizes, int n_in,
                              void* d_out, int out_size) {
    const float* in = (const float*)d_in[0];
    const int*   hm = (const int*)d_in[1];
    const int*   vm = (const int*)d_in[2];
    float*       out = (float*)d_out;

    sum_kernel<<<GRID_A, NTHREADS>>>(in, hm, vm);

    const int total4 = HH * WW * (CC / 4);            // 9,437,184
    bcast_kernel<<<total4 / 256, 256>>>(reinterpret_cast<float4*>(out));
}

// round 14
// speedup vs baseline: 1.0832x; 1.0832x over previous
#include <cuda_runtime.h>

#define HH 768
#define WW 768
#define CC 64
#define NSEG 385
#define NTHREADS 64
#define PER_T (HH / NTHREADS)     // 12 mask elems per scan thread
#define GRID_A 4736               // 148 SM x 32 CTA slots
#define NWARPS_TOTAL (GRID_A * 2)

// ---- scratch (device globals; no allocations allowed) ----
__device__ float4 g_cellmean[(size_t)NSEG * NSEG * 16];   // compact, ~9.4MB used
__device__ int    g_row_id_d[HH];
__device__ int    g_col_id_d[WW];
__device__ int    g_row_cell[HH];    // row_id[y] * ncol (precomputed cell base)
__device__ int    g_ncol_d;

// ---------------------------------------------------------------------------
// Kernel A: per-cell means (R8-exact sum loop), no broadcast.
//   prolog: every block redundantly scans both masks -> SMEM segment tables;
//           block 0 publishes per-pixel row/col ids, then row_id*ncol bases.
//   main:   warp-per-cell, lanes = 16 channel-quads x 2 x-parities,
//           512B contiguous warp access, ONE shfl_xor(16) reduce,
//           256B result store to compact cellmean (L2-resident for kernel B).
// ---------------------------------------------------------------------------
__global__ void __launch_bounds__(NTHREADS, 32)
sum_kernel(const float* __restrict__ in,
           const int* __restrict__ h_mask,
           const int* __restrict__ v_mask) {
    __shared__ int s_row_start[NSEG + 1];
    __shared__ int s_col_start[NSEG + 1];
    __shared__ int s_tmp[2];
    __shared__ int s_nrow, s_ncol;

    const int t = threadIdx.x;
    const int lane = t & 31, w = t >> 5;
    const bool pub = (blockIdx.x == 0);

    // ---- prolog: build segment starts for both masks ----
    #pragma unroll
    for (int axis = 0; axis < 2; ++axis) {
        const int* m = (axis == 0) ? h_mask : v_mask;
        int* start   = (axis == 0) ? s_row_start : s_col_start;
        int* gid     = (axis == 0) ? g_row_id_d : g_col_id_d;

        const int base = t * PER_T;
        int pm = (base == 0) ? 1 : m[base - 1];   // pm=1 at i=0 forces rise[0]=0
        int rises = 0, cnt = 0;
        #pragma unroll
        for (int k = 0; k < PER_T; ++k) {
            const int mv = m[base + k];
            const int r = (mv == 1 && pm == 0);
            rises |= (r << k);
            cnt += r;
            pm = mv;
        }
        int v = cnt;
        #pragma unroll
        for (int o = 1; o < 32; o <<= 1) {
            int n = __shfl_up_sync(0xFFFFFFFFu, v, o);
            if (lane >= o) v += n;
        }
        if (lane == 31) s_tmp[w] = v;
        __syncthreads();
        const int add   = (w == 1) ? s_tmp[0] : 0;
        const int total = s_tmp[0] + s_tmp[1];
        const int excl  = v + add - cnt;

        int sid = excl;
        #pragma unroll
        for (int k = 0; k < PER_T; ++k) {
            if ((rises >> k) & 1) { ++sid; start[sid] = base + k; }
            if (pub) gid[base + k] = sid;
        }
        const int nseg = total + 1;
        if (t == 0) {
            start[0] = 0; start[nseg] = HH;
            if (axis == 0) s_nrow = nseg;
            else { s_ncol = nseg; if (pub) g_ncol_d = nseg; }
        }
        __syncthreads();
    }

    const int nrow = s_nrow, ncol = s_ncol;
    const int total_cells = nrow * ncol;

    // block 0: publish precomputed row cell bases (row_id * ncol)
    if (pub) {
        #pragma unroll
        for (int k = 0; k < PER_T; ++k) {
            const int yy = t * PER_T + k;
            g_row_cell[yy] = g_row_id_d[yy] * ncol;
        }
    }

    const int cg = lane & 15;     // channel quad
    const int xo = lane >> 4;     // x parity
    const int gw = blockIdx.x * 2 + w;

    // ---- main: warp-per-cell grid-stride (R8-exact, unroll 2) ----
    for (int cell = gw; cell < total_cells; cell += NWARPS_TOTAL) {
        const int rseg = cell / ncol;
        const int cseg = cell - rseg * ncol;
        const int cs = s_col_start[cseg], ce = s_col_start[cseg + 1];
        const int rs = s_row_start[rseg], re = s_row_start[rseg + 1];

        float4 a0 = make_float4(0.f, 0.f, 0.f, 0.f);
        float4 a1 = make_float4(0.f, 0.f, 0.f, 0.f);

        int y = rs;
        for (; y + 1 < re; y += 2) {
            const float4* r0 = reinterpret_cast<const float4*>(
                in + (size_t)y * WW * CC);
            const float4* r1 = r0 + WW * (CC / 4);
            #pragma unroll 2
            for (int x = cs + xo; x < ce; x += 2) {
                const float4 v0 = __ldcs(&r0[x * 16 + cg]);
                const float4 v1 = __ldcs(&r1[x * 16 + cg]);
                a0.x += v0.x; a0.y += v0.y; a0.z += v0.z; a0.w += v0.w;
                a1.x += v1.x; a1.y += v1.y; a1.z += v1.z; a1.w += v1.w;
            }
        }
        if (y < re) {
            const float4* r0 = reinterpret_cast<const float4*>(
                in + (size_t)y * WW * CC);
            #pragma unroll 2
            for (int x = cs + xo; x < ce; x += 2) {
                const float4 v0 = __ldcs(&r0[x * 16 + cg]);
                a0.x += v0.x; a0.y += v0.y; a0.z += v0.z; a0.w += v0.w;
            }
        }
        a0.x += a1.x; a0.y += a1.y; a0.z += a1.z; a0.w += a1.w;

        // single-stage reduce across the two x parities (lanes +-16)
        a0.x += __shfl_xor_sync(0xFFFFFFFFu, a0.x, 16);
        a0.y += __shfl_xor_sync(0xFFFFFFFFu, a0.y, 16);
        a0.z += __shfl_xor_sync(0xFFFFFFFFu, a0.z, 16);
        a0.w += __shfl_xor_sync(0xFFFFFFFFu, a0.w, 16);

        if (xo == 0) {
            const float inv = 1.0f / (float)((re - rs) * (ce - cs));
            g_cellmean[(size_t)cell * 16 + cg] =
                make_float4(a0.x * inv, a0.y * inv, a0.z * inv, a0.w * inv);
        }
    }
}

// ---------------------------------------------------------------------------
// Kernel B: broadcast, latency-optimized.
//   grid = (12, 768): blockIdx.y = pixel row (no division), each thread does
//   4 INDEPENDENT gather->store chains (ILP=4), each sweep a contiguous
//   4KB coalesced run. Chain per store: col_id[x] (L1/L2 hot) -> cellmean
//   (L2 hot) -> __stcs store. Row cell base is one L1-broadcast load.
//   Row = 12288 float4; 12 blocks x 256 thr x 4 = 12288. Exact cover.
// ---------------------------------------------------------------------------
#define B_ILP 4
#define ROW_F4 (WW * (CC / 4))            // 12288 float4 per pixel row
#define B_BLOCKS_X (ROW_F4 / (256 * B_ILP))   // 12

__global__ void __launch_bounds__(256)
bcast_kernel(float4* __restrict__ out) {
    const int y = blockIdx.y;
    const int rowbase_cell = __ldg(&g_row_cell[y]);
    float4* rowp = out + (size_t)y * ROW_F4;

    const int tid0 = blockIdx.x * 256 + threadIdx.x;

    #pragma unroll
    for (int k = 0; k < B_ILP; ++k) {
        const int i = tid0 + k * (B_BLOCKS_X * 256);   // stride 3072
        const int x = i >> 4;
        const int q = i & 15;
        const int cell = rowbase_cell + __ldg(&g_col_id_d[x]);
        const float4 v = __ldg(&g_cellmean[(size_t)cell * 16 + q]);
        __stcs(&rowp[i], v);
    }
}

// ---------------------------------------------------------------------------
extern "C" void kernel_launch(void* const* d_in, const int* in_sizes, int n_in,
                              void* d_out, int out_size) {
    const float* in = (const float*)d_in[0];
    const int*   hm = (const int*)d_in[1];
    const int*   vm = (const int*)d_in[2];
    float*       out = (float*)d_out;

    sum_kernel<<<GRID_A, NTHREADS>>>(in, hm, vm);
    bcast_kernel<<<dim3(B_BLOCKS_X, HH), 256>>>(reinterpret_cast<float4*>(out));
}